// round 15
// baseline (speedup 1.0000x reference)
#include <cuda_runtime.h>

#define BN 65536
#define DD 512
#define CC 50
#define NE (BN + CC)
#define FK 10
#define NPADB 56             // class dim padded to 56 (7 n-tiles of 8)
#define NT 7
#define TPB 256              // 8 warps
#define BROWS 128            // rows per GEMM block (1 m-tile of 16 per warp)
#define HB 8192
#define HSCALE 2048.0f
#define CAP 8192

// smem float-offsets (BROWS=128)
#define A_STRIDE 36
#define ASTAGE   4608         // 128*36 per stage
#define MAIN_BH  9216         // + bf*1792
#define MAIN_NORM 12800
#define MAIN_BIAS 12928
#define SMEM_MAIN 12992       // floats (51,968 B)
#define OUT_BHI  9216         // + bf*896 (u32)
#define OUT_BLO  11008        // + bf*896 (u32)
#define SMEM_OUT 12800        // floats (51,200 B)
#define SL_STRIDE 58          // logits at offset 0 (A region), 128*58=7424
// topkcent scratch in stage-1 A region [4608,9216)
#define TC_SH   4608          // 256 u64 -> 512 floats
#define TC_IDX  5120          // 10 ints
#define TC_W    5136          // 10 floats
#define TC_SCOL 5152          // 512 floats
#define TC_RED  5664          // 256 floats

// ---------------- device state ----------------
__device__ double g_sum_ent;
__device__ float  g_ent[NE];
__device__ float  g_conf[NE];
__device__ int    g_lab[NE];
__device__ float  g_scale[BN];
__device__ __align__(16) unsigned g_hist16[HB];
__device__ int    g_cand_n[2];
__device__ int    g_done;
__device__ int    g_cent_done;
__device__ int    g_valid_n;
__device__ int    g_valid_idx[BN];
__device__ float  g_cand[2][CAP];
__device__ float  g_thr, g_conf_thr;
__device__ __align__(16) float    g_WThi[DD * NPADB];       // W^T tf32-hi
__device__ __align__(16) unsigned g_CBhi[(DD / 2) * NPADB]; // centroids^T bf16x2 hi
__device__ __align__(16) unsigned g_CBlo[(DD / 2) * NPADB]; // centroids^T bf16x2 lo

// ---------------- helpers ----------------
__device__ __forceinline__ unsigned fkey(float f) {
    unsigned u = __float_as_uint(f);
    return (u & 0x80000000u) ? ~u : (u | 0x80000000u);
}
__device__ __forceinline__ int ent_bucket(float e) {
    int b = (int)(e * HSCALE);
    return min(max(b, 0), HB - 1);
}
__device__ __forceinline__ unsigned tf32_rnd(float x) {
    unsigned r;
    asm("cvt.rna.tf32.f32 %0, %1;" : "=r"(r) : "f"(x));
    return r;
}
__device__ __forceinline__ void mma8(float* d, const unsigned* a,
                                     unsigned b0, unsigned b1) {
    asm volatile(
        "mma.sync.aligned.m16n8k8.row.col.f32.tf32.tf32.f32 "
        "{%0,%1,%2,%3},{%4,%5,%6,%7},{%8,%9},{%0,%1,%2,%3};"
        : "+f"(d[0]), "+f"(d[1]), "+f"(d[2]), "+f"(d[3])
        : "r"(a[0]), "r"(a[1]), "r"(a[2]), "r"(a[3]), "r"(b0), "r"(b1));
}
__device__ __forceinline__ void mma16(float* d, const unsigned* a,
                                      unsigned b0, unsigned b1) {
    asm volatile(
        "mma.sync.aligned.m16n8k16.row.col.f32.bf16.bf16.f32 "
        "{%0,%1,%2,%3},{%4,%5,%6,%7},{%8,%9},{%0,%1,%2,%3};"
        : "+f"(d[0]), "+f"(d[1]), "+f"(d[2]), "+f"(d[3])
        : "r"(a[0]), "r"(a[1]), "r"(a[2]), "r"(a[3]), "r"(b0), "r"(b1));
}
__device__ __forceinline__ unsigned packbf(float e, float o) {
    unsigned r;
    asm("cvt.rn.bf16x2.f32 %0, %1, %2;" : "=r"(r) : "f"(o), "f"(e));
    return r;
}
__device__ __forceinline__ void split2(float e, float o, unsigned &hi, unsigned &lo) {
    hi = packbf(e, o);
    float fe = __uint_as_float(hi << 16);
    float fo = __uint_as_float(hi & 0xffff0000u);
    lo = packbf(e - fe, o - fo);
}
__device__ __forceinline__ void cpa16(unsigned dst, const void* src) {
    asm volatile("cp.async.ca.shared.global [%0], [%1], 16;" :: "r"(dst), "l"(src));
}
#define CP_COMMIT() asm volatile("cp.async.commit_group;")
#define CP_WAIT1()  asm volatile("cp.async.wait_group 1;")
#define CP_WAIT0()  asm volatile("cp.async.wait_group 0;")

// ---------------- 1) warmup stats + W split + state reset ----------------
__global__ void k_warmup(const float* __restrict__ W, const float* __restrict__ b) {
    int c1 = blockIdx.x, tid = threadIdx.x;     // 50 blocks x 64
    __shared__ float sw[DD];
    __shared__ float sl[CC];
    for (int k = tid; k < DD; k += 64) sw[k] = W[(size_t)c1 * DD + k];
    __syncthreads();
    if (tid < CC) {
        const float* wj = W + (size_t)tid * DD;
        float acc = 0.f;
        for (int k = 0; k < DD; k++) acc += sw[k] * wj[k];
        sl[tid] = acc + b[tid];
    }
    __syncthreads();
    if (tid == 0) {
        float mx = sl[0]; int arg = 0;
        for (int c = 1; c < CC; c++) if (sl[c] > mx) { mx = sl[c]; arg = c; }
        float se = 0.f, sw2 = 0.f;
        for (int c = 0; c < CC; c++) {
            float e = __expf(sl[c] - mx);
            se += e; sw2 += e * sl[c];
        }
        float lse = mx + __logf(se);
        g_ent[c1]  = lse - sw2 / se;
        g_conf[c1] = 1.0f / se;
        g_lab[c1]  = arg;
    }
    int g = blockIdx.x * 64 + tid;
    for (int i = g; i < HB; i += CC * 64) g_hist16[i] = 0u;
    for (int idx = g; idx < DD * NPADB; idx += CC * 64) {   // W^T tf32-hi split
        int k = idx / NPADB, c = idx % NPADB;
        float x = (c < CC) ? W[(size_t)c * DD + k] : 0.f;
        g_WThi[idx] = __uint_as_float(tf32_rnd(x));
    }
    if (c1 == 0 && tid == 0) {
        g_sum_ent = 0.0;
        g_cand_n[0] = 0; g_cand_n[1] = 0;
        g_done = 0;
        g_cent_done = 0;
        g_valid_n = 0;
    }
}

// ---------------- 2) main GEMM (1xTF32) + stats + superset compaction -----
__global__ __launch_bounds__(TPB, 4)
void k_main(const float* __restrict__ feat, const float* __restrict__ lraw,
            const float* __restrict__ laug, const float* __restrict__ b) {
    extern __shared__ float smem[];
    __shared__ double red[TPB];
    int tid = threadIdx.x;
    int lane = tid & 31, wb = (tid >> 5) * 16, r4 = lane >> 2, q4 = lane & 3;
    unsigned sb = (unsigned)__cvta_generic_to_shared(smem);
    const float* featBase = feat + (size_t)blockIdx.x * BROWS * DD;

    if (tid < NPADB) smem[MAIN_BIAS + tid] = (tid < CC) ? b[tid] : 0.f;

    float acc[28];
#pragma unroll
    for (int j = 0; j < 28; j++) acc[j] = 0.f;
    float norm0 = 0.f, norm1 = 0.f;

#define ISSUE_MAIN(kc, bf)                                                       \
    {                                                                            \
        int _kc = (kc), _bf = (bf);                                              \
        _Pragma("unroll")                                                        \
        for (int n = 0; n < 4; n++) {                                            \
            int i = tid + n * TPB;           /* 128 rows x 8 quads */            \
            int row = i >> 3, q = i & 7;                                         \
            cpa16(sb + (unsigned)(_bf * ASTAGE + row * A_STRIDE + q * 4) * 4u,   \
                  featBase + (size_t)row * DD + _kc * 32 + q * 4);               \
        }                                                                        \
        for (int i = tid; i < 448; i += TPB) {                                   \
            int row = i / 14, q = i % 14;                                        \
            cpa16(sb + (unsigned)(MAIN_BH + _bf * 1792 + row * NPADB + q * 4) * 4u,\
                  g_WThi + (size_t)(_kc * 32 + row) * NPADB + q * 4);            \
        }                                                                        \
    }

    ISSUE_MAIN(0, 0);
    CP_COMMIT();
#pragma unroll 1
    for (int c = 0; c < 16; ++c) {
        int bf = c & 1;
        if (c + 1 < 16) {
            ISSUE_MAIN(c + 1, (c + 1) & 1);
            CP_COMMIT();
            CP_WAIT1();
        } else {
            CP_WAIT0();
        }
        __syncthreads();
        const float* sA  = smem + bf * ASTAGE;
        const float* sBH = smem + MAIN_BH + bf * 1792;
#pragma unroll
        for (int kt = 0; kt < 4; kt++) {
            int k0 = kt * 8 + q4;
            float af[4];
            af[0] = sA[(wb + r4) * A_STRIDE + k0];
            af[1] = sA[(wb + r4 + 8) * A_STRIDE + k0];
            af[2] = sA[(wb + r4) * A_STRIDE + k0 + 4];
            af[3] = sA[(wb + r4 + 8) * A_STRIDE + k0 + 4];
            unsigned ahi[4];
#pragma unroll
            for (int j = 0; j < 4; j++) ahi[j] = tf32_rnd(af[j]);
            norm0 = fmaf(af[0], af[0], fmaf(af[2], af[2], norm0));
            norm1 = fmaf(af[1], af[1], fmaf(af[3], af[3], norm1));
#pragma unroll
            for (int nt = 0; nt < NT; nt++) {
                int bi = k0 * NPADB + nt * 8 + r4;
                unsigned bh0 = __float_as_uint(sBH[bi]);
                unsigned bh1 = __float_as_uint(sBH[bi + 4 * NPADB]);
                mma8(acc + nt * 4, ahi, bh0, bh1);
            }
        }
        __syncthreads();
    }
#undef ISSUE_MAIN

    // norms: reduce across quad, store per row
    norm0 += __shfl_xor_sync(0xffffffffu, norm0, 1);
    norm0 += __shfl_xor_sync(0xffffffffu, norm0, 2);
    norm1 += __shfl_xor_sync(0xffffffffu, norm1, 1);
    norm1 += __shfl_xor_sync(0xffffffffu, norm1, 2);
    if (q4 == 0) {
        smem[MAIN_NORM + wb + r4]     = norm0;
        smem[MAIN_NORM + wb + 8 + r4] = norm1;
    }

    // ---- dual-view argmax consistency (staged coalesced in A region) ----
    int i1 = 0, i2 = 0;
    {
        const float* srcR = lraw + (size_t)blockIdx.x * BROWS * CC;
        for (int i = tid; i < BROWS * CC; i += TPB) smem[i] = srcR[i];
        __syncthreads();
        if (tid < BROWS) {
            const float* rr = smem + tid * CC;
            float b1 = -3.4e38f;
#pragma unroll
            for (int c = 0; c < CC; c++)
                if (rr[c] > b1) { b1 = rr[c]; i1 = c; }
        }
        __syncthreads();
        const float* srcA = laug + (size_t)blockIdx.x * BROWS * CC;
        for (int i = tid; i < BROWS * CC; i += TPB) smem[i] = srcA[i];
        __syncthreads();
        if (tid < BROWS) {
            const float* rr = smem + tid * CC;
            float b2 = -3.4e38f;
#pragma unroll
            for (int c = 0; c < CC; c++)
                if (rr[c] > b2) { b2 = rr[c]; i2 = c; }
        }
        __syncthreads();
    }

    // scatter logit fragments to smem [row][58] (A region reused)
#pragma unroll
    for (int nt = 0; nt < NT; nt++) {
        int row = wb + r4;
        int col = nt * 8 + q4 * 2;
        const float* d = acc + nt * 4;
        *(float2*)(smem + row * SL_STRIDE + col) = make_float2(d[0], d[1]);
        *(float2*)(smem + (row + 8) * SL_STRIDE + col) = make_float2(d[2], d[3]);
    }
    __syncthreads();

    // ---- exact fp32 per-row epilogue (no lg[] array: two smem passes) ----
    float ent = 0.f;
    if (tid < BROWS) {
        int grow = blockIdx.x * BROWS + tid;
        const float* lrow = smem + tid * SL_STRIDE;
        const float* brow = smem + MAIN_BIAS;
        float mx = -3.4e38f; int arg = 0;
#pragma unroll
        for (int c = 0; c < CC; c++) {
            float v = lrow[c] + brow[c];
            if (v > mx) { mx = v; arg = c; }
        }
        float se = 0.f, sl = 0.f;
#pragma unroll
        for (int c = 0; c < CC; c++) {
            float v = lrow[c] + brow[c];
            float e = __expf(v - mx);
            se += e; sl += e * v;
        }
        float lse  = mx + __logf(se);
        ent        = lse - sl / se;
        float pmax = 1.0f / se;
        float inv  = 1.0f / fmaxf(sqrtf(smem[MAIN_NORM + tid]), 1e-12f);

        g_ent[CC + grow]  = ent;
        g_conf[CC + grow] = pmax;
        g_lab[CC + grow]  = arg;
        g_scale[grow]     = 20.0f * inv;
        atomicAdd(&g_hist16[ent_bucket(ent)], 1u);

        // superset compaction: consist && conf >= 0.62 (looser of both branches)
        if ((i1 == i2) && (pmax >= 0.62f)) {
            int p = atomicAdd(&g_valid_n, 1);
            g_valid_idx[p] = CC + grow;
        }
    }

    red[tid] = (tid < BROWS) ? (double)ent : 0.0;
    __syncthreads();
    for (int s = TPB / 2; s; s >>= 1) {
        if (tid < s) red[tid] += red[tid + s];
        __syncthreads();
    }
    if (tid == 0) atomicAdd(&g_sum_ent, red[0]);
}

// -------- 3) fused scan + candidate gather + tail-block exact pick --------
__global__ void k_selectscan() {
    __shared__ unsigned sc[1024];
    __shared__ int   s_bucket[2], s_rwith[2];
    __shared__ float qv[2];
    __shared__ int   s_last;
    int tid = threadIdx.x;                       // 64 blocks x 1024

    float m = (float)(g_sum_ent / (double)BN);
    float q = (m >= 0.45f) ? 0.25f : ((m >= 0.38f) ? 0.3f : 0.4f);
    float pos = q * (float)(BN - 1);
    float lof = floorf(pos);
    float frac = pos - lof;
    int rank0 = (int)lof;
    int rank1 = min((int)lof + 1, BN - 1);
    if (blockIdx.x == 0 && tid == 0)
        g_conf_thr = (m >= 0.45f) ? 0.72f : 0.62f;

    int base = tid * 8;
    uint4 h0 = *(const uint4*)&g_hist16[base];
    uint4 h1 = *(const uint4*)&g_hist16[base + 4];
    unsigned bins[8] = {h0.x, h0.y, h0.z, h0.w, h1.x, h1.y, h1.z, h1.w};
    unsigned local = 0;
#pragma unroll
    for (int j = 0; j < 8; j++) local += bins[j];
    sc[tid] = local;
    __syncthreads();
    for (int off = 1; off < 1024; off <<= 1) {
        unsigned v = 0;
        if (tid >= off) v = sc[tid - off];
        __syncthreads();
        if (tid >= off) sc[tid] += v;
        __syncthreads();
    }
    unsigned incl = sc[tid];
    unsigned before = incl - local;
    int ranks[2] = {rank0, rank1};
#pragma unroll
    for (int s = 0; s < 2; s++) {
        unsigned r = (unsigned)ranks[s];
        if (before <= r && r < incl) {
            unsigned acc = before;
#pragma unroll
            for (int j = 0; j < 8; j++) {
                if (r < acc + bins[j]) {
                    s_bucket[s] = base + j;
                    s_rwith[s]  = (int)(r - acc);
                    break;
                }
                acc += bins[j];
            }
        }
    }
    __syncthreads();

    int i = blockIdx.x * 1024 + tid;
    int b0 = s_bucket[0], b1 = s_bucket[1];
    float e = g_ent[CC + i];
    int bb = ent_bucket(e);
    if (bb == b0) {
        int p = atomicAdd(&g_cand_n[0], 1);
        if (p < CAP) g_cand[0][p] = e;
    }
    if (bb == b1) {
        int p = atomicAdd(&g_cand_n[1], 1);
        if (p < CAP) g_cand[1][p] = e;
    }
    __threadfence();
    __syncthreads();
    if (tid == 0) s_last = (atomicAdd(&g_done, 1) == 63);
    __syncthreads();
    if (!s_last) return;
    __threadfence();

    for (int s = 0; s < 2; s++) {
        int n = min(atomicAdd(&g_cand_n[s], 0), CAP);
        int r = s_rwith[s];
        for (int k = tid; k < n; k += 1024) {
            float v = g_cand[s][k];
            int rank = 0;
            for (int j = 0; j < n; j++) {
                float u = g_cand[s][j];
                rank += (u < v) || (u == v && j < k);
            }
            if (rank == r) qv[s] = v;
        }
        __syncthreads();
    }
    if (tid == 0) g_thr = qv[0] * (1.0f - frac) + qv[1] * frac;
}

// ---- topk + centroid for one class over compacted superset ----
__device__ void topk_centroid(int c, int tid, int nv, float* smem,
                              const float* __restrict__ feat,
                              const float* __restrict__ W) {
    float thr = g_thr, cthr = g_conf_thr;
    unsigned long long* sh = (unsigned long long*)(smem + TC_SH);
    int*   s_idx = (int*)(smem + TC_IDX);
    float* s_w   = smem + TC_W;
    float* scol  = smem + TC_SCOL;
    float* red   = smem + TC_RED;

    unsigned long long loc[FK];
#pragma unroll
    for (int j = 0; j < FK; j++) loc[j] = ~0ull;

    for (int t = tid; t < CC + nv; t += 256) {
        int e = (t < CC) ? t : g_valid_idx[t - CC];
        if (g_lab[e] != c) continue;
        if (e >= CC && ((g_ent[e] > thr) || (g_conf[e] < cthr))) continue;
        unsigned long long k =
            (((unsigned long long)fkey(g_ent[e])) << 32) | (unsigned)e;
        if (k < loc[FK - 1]) {
            loc[FK - 1] = k;
#pragma unroll
            for (int j = FK - 1; j > 0; j--) {
                if (loc[j] < loc[j - 1]) {
                    unsigned long long t2 = loc[j];
                    loc[j] = loc[j - 1];
                    loc[j - 1] = t2;
                }
            }
        }
    }

    int ptr = 0;
    for (int j = 0; j < FK; j++) {
        sh[tid] = (ptr < FK) ? loc[ptr] : ~0ull;
        __syncthreads();
        for (int s = 128; s; s >>= 1) {
            if (tid < s) {
                unsigned long long x = sh[tid], y = sh[tid + s];
                sh[tid] = (y < x) ? y : x;
            }
            __syncthreads();
        }
        unsigned long long win = sh[0];
        __syncthreads();
        if (ptr < FK && loc[ptr] == win && win != ~0ull) ptr++;
        if (tid == 0) {
            if (win != ~0ull) {
                int idx = (int)(win & 0xffffffffu);
                s_idx[j] = idx;
                s_w[j]   = fmaxf(g_conf[idx], 1e-6f);
            } else {
                s_idx[j] = -1;
            }
        }
        __syncthreads();
    }

    float a0 = 0.f, a1 = 0.f;
    for (int j = 0; j < FK; j++) {
        int idx = s_idx[j];
        if (idx >= 0) {
            const float* v = (idx < CC) ? (W + (size_t)idx * DD)
                                        : (feat + (size_t)(idx - CC) * DD);
            float x0 = v[tid], x1 = v[tid + 256];
            red[tid] = x0 * x0 + x1 * x1;
            __syncthreads();
            for (int s = 128; s; s >>= 1) {
                if (tid < s) red[tid] += red[tid + s];
                __syncthreads();
            }
            float w = s_w[j] / fmaxf(sqrtf(red[0]), 1e-12f);
            __syncthreads();
            a0 += w * x0;
            a1 += w * x1;
        }
    }
    red[tid] = a0 * a0 + a1 * a1;
    __syncthreads();
    for (int s = 128; s; s >>= 1) {
        if (tid < s) red[tid] += red[tid + s];
        __syncthreads();
    }
    float n = fmaxf(sqrtf(red[0]), 1e-12f);
    scol[tid]       = a0 / n;
    scol[tid + 256] = a1 / n;
    __syncthreads();
    {
        float e = scol[2 * tid], o = scol[2 * tid + 1];
        unsigned hi, lo;
        split2(e, o, hi, lo);
        g_CBhi[(size_t)tid * NPADB + c] = hi;
        g_CBlo[(size_t)tid * NPADB + c] = lo;
    }
    if (c == 0) {
#pragma unroll
        for (int p = CC; p < NPADB; p++) {
            g_CBhi[(size_t)tid * NPADB + p] = 0u;
            g_CBlo[(size_t)tid * NPADB + p] = 0u;
        }
    }
    __syncthreads();
}

// ---- 4) fused: centroid (blocks 0-49) + output GEMM (all 512) ----
__global__ __launch_bounds__(TPB, 4)
void k_out(const float* __restrict__ feat, const float* __restrict__ W,
           float* __restrict__ out) {
    extern __shared__ float smem[];
    int tid = threadIdx.x;
    int lane = tid & 31, wb = (tid >> 5) * 16, r4 = lane >> 2, q4 = lane & 3;
    unsigned sb = (unsigned)__cvta_generic_to_shared(smem);
    const float* featBase = feat + (size_t)blockIdx.x * BROWS * DD;

#define ISSUE_A(kc, bf)                                                          \
    {                                                                            \
        int _kc = (kc), _bf = (bf);                                              \
        _Pragma("unroll")                                                        \
        for (int n = 0; n < 4; n++) {                                            \
            int i = tid + n * TPB;                                               \
            int row = i >> 3, q = i & 7;                                         \
            cpa16(sb + (unsigned)(_bf * ASTAGE + row * A_STRIDE + q * 4) * 4u,   \
                  featBase + (size_t)row * DD + _kc * 32 + q * 4);               \
        }                                                                        \
    }
#define ISSUE_B(kc, bf)                                                          \
    if (tid < 224) {                                                             \
        int _kc = (kc), _bf = (bf);                                              \
        int row = tid / 14, q = tid % 14;                                        \
        cpa16(sb + (unsigned)(OUT_BHI + _bf * 896 + row * NPADB + q * 4) * 4u,   \
              g_CBhi + (size_t)(_kc * 16 + row) * NPADB + q * 4);                \
        cpa16(sb + (unsigned)(OUT_BLO + _bf * 896 + row * NPADB + q * 4) * 4u,   \
              g_CBlo + (size_t)(_kc * 16 + row) * NPADB + q * 4);                \
    }

    // A chunk-0 (stage 0) overlaps the centroid prologue (stage-1 region)
    ISSUE_A(0, 0);
    CP_COMMIT();                                  // group 1 = A0

    if (blockIdx.x < CC) {
        int nv = g_valid_n;
        topk_centroid(blockIdx.x, tid, nv, smem, feat, W);
        __threadfence();
        __syncthreads();
        if (tid == 0) atomicAdd(&g_cent_done, 1);
    }
    if (tid == 0) {
        volatile int* vd = &g_cent_done;
        while (*vd < CC) __nanosleep(100);
    }
    __syncthreads();
    __threadfence();

    ISSUE_B(0, 0);
    CP_COMMIT();                                  // group 2 = B0
    ISSUE_A(1, 1); ISSUE_B(1, 1);
    CP_COMMIT();                                  // group 3 = chunk 1

    float acc[28];
#pragma unroll
    for (int j = 0; j < 28; j++) acc[j] = 0.f;

#pragma unroll 1
    for (int c = 0; c < 16; ++c) {
        int bf = c & 1;
        if (c == 15) { CP_WAIT0(); } else { CP_WAIT1(); }
        __syncthreads();
        const float* sA = smem + bf * ASTAGE;
        const unsigned* sBH = (const unsigned*)(smem + OUT_BHI + bf * 896);
        const unsigned* sBL = (const unsigned*)(smem + OUT_BLO + bf * 896);
#pragma unroll
        for (int kt = 0; kt < 2; kt++) {
            int k0 = kt * 16 + 2 * q4;
            unsigned ahi[4], alo[4];
            {
                int rb = wb + r4;
                float2 x0 = *(const float2*)&sA[rb * A_STRIDE + k0];
                float2 x1 = *(const float2*)&sA[(rb + 8) * A_STRIDE + k0];
                float2 x2 = *(const float2*)&sA[rb * A_STRIDE + k0 + 8];
                float2 x3 = *(const float2*)&sA[(rb + 8) * A_STRIDE + k0 + 8];
                split2(x0.x, x0.y, ahi[0], alo[0]);
                split2(x1.x, x1.y, ahi[1], alo[1]);
                split2(x2.x, x2.y, ahi[2], alo[2]);
                split2(x3.x, x3.y, ahi[3], alo[3]);
            }
#pragma unroll
            for (int nt = 0; nt < NT; nt++) {
                int n = nt * 8 + r4;
                int kp = kt * 8 + q4;
                unsigned bh0 = sBH[kp * NPADB + n];
                unsigned bh1 = sBH[(kp + 4) * NPADB + n];
                unsigned bl0 = sBL[kp * NPADB + n];
                unsigned bl1 = sBL[(kp + 4) * NPADB + n];
                float* d0 = acc + nt * 4;
                mma16(d0, ahi, bh0, bh1);
                mma16(d0, alo, bh0, bh1);
                mma16(d0, ahi, bl0, bl1);
            }
        }
        __syncthreads();
        if (c + 2 < 16) {                         // refill THIS buffer
            ISSUE_A(c + 2, bf); ISSUE_B(c + 2, bf);
            CP_COMMIT();
        }
    }
#undef ISSUE_A
#undef ISSUE_B

#pragma unroll
    for (int nt = 0; nt < NT; nt++) {
        int row = wb + r4;
        int col = nt * 8 + q4 * 2;
        const float* d = acc + nt * 4;
        *(float2*)(smem + row * SL_STRIDE + col) = make_float2(d[0], d[1]);
        *(float2*)(smem + (row + 8) * SL_STRIDE + col) = make_float2(d[2], d[3]);
    }
    __syncthreads();

    if (tid < BROWS) {
        int grow = blockIdx.x * BROWS + tid;
        float s = g_scale[grow];
        float2* o2 = (float2*)(out + (size_t)grow * CC);
#pragma unroll
        for (int j = 0; j < CC / 2; j++) {
            float2 v;
            v.x = s * smem[tid * SL_STRIDE + 2 * j];
            v.y = s * smem[tid * SL_STRIDE + 2 * j + 1];
            o2[j] = v;
        }
    }
}

// ---------------- host ----------------
extern "C" void kernel_launch(void* const* d_in, const int* in_sizes, int n_in,
                              void* d_out, int out_size) {
    const float* feat = (const float*)d_in[0];
    const float* lraw = (const float*)d_in[1];
    const float* laug = (const float*)d_in[2];
    const float* W    = (const float*)d_in[3];
    const float* b    = (const float*)d_in[4];
    float* out = (float*)d_out;

    size_t sh_main = (size_t)SMEM_MAIN * sizeof(float);  // 51,968 B
    size_t sh_out  = (size_t)SMEM_OUT  * sizeof(float);  // 51,200 B
    cudaFuncSetAttribute(k_main, cudaFuncAttributeMaxDynamicSharedMemorySize, (int)sh_main);
    cudaFuncSetAttribute(k_out,  cudaFuncAttributeMaxDynamicSharedMemorySize, (int)sh_out);

    k_warmup<<<CC, 64>>>(W, b);                                 // 1
    k_main<<<BN / BROWS, TPB, sh_main>>>(feat, lraw, laug, b);  // 2
    k_selectscan<<<64, 1024>>>();                               // 3
    k_out<<<BN / BROWS, TPB, sh_out>>>(feat, W, out);           // 4 <- ncu window
}

// round 16
// speedup vs baseline: 1.0136x; 1.0136x over previous
#include <cuda_runtime.h>

#define BN 65536
#define DD 512
#define CC 50
#define NE (BN + CC)
#define FK 10
#define NPADB 56             // class dim padded to 56 (7 n-tiles of 8)
#define NT 7
#define TPB 256              // 8 warps
#define BROWS 128            // rows per GEMM block (1 m-tile of 16 per warp)
#define HB 8192
#define HSCALE 2048.0f
#define CAP 8192

// smem float-offsets (BROWS=128)
#define A_STRIDE 36
#define ASTAGE   4608         // 128*36 per stage
#define MAIN_BH  9216         // + bf*1792
#define MAIN_NORM 12800
#define MAIN_BIAS 12928
#define SMEM_MAIN 12992       // floats (51,968 B)
#define OUT_BHI  9216         // + bf*896 (u32)
#define OUT_BLO  11008        // + bf*896 (u32)
#define SMEM_OUT 12800        // floats (51,200 B)
#define SL_STRIDE 58          // logits at offset 0 (A region)

// ---------------- device state ----------------
__device__ double g_sum_ent;
__device__ float  g_ent[NE];
__device__ float  g_conf[NE];
__device__ int    g_lab[NE];
__device__ float  g_scale[BN];
__device__ __align__(16) unsigned g_hist16[HB];
__device__ int    g_cand_n[2];
__device__ int    g_done;
__device__ int    g_thr_flag;
__device__ int    g_valid_n;
__device__ int    g_valid_idx[BN];
__device__ float  g_cand[2][CAP];
__device__ float  g_thr, g_conf_thr;
__device__ __align__(16) float    g_WThi[DD * NPADB];       // W^T tf32-hi
__device__ __align__(16) unsigned g_CBhi[(DD / 2) * NPADB]; // centroids^T bf16x2 hi
__device__ __align__(16) unsigned g_CBlo[(DD / 2) * NPADB]; // centroids^T bf16x2 lo

// ---------------- helpers ----------------
__device__ __forceinline__ unsigned fkey(float f) {
    unsigned u = __float_as_uint(f);
    return (u & 0x80000000u) ? ~u : (u | 0x80000000u);
}
__device__ __forceinline__ int ent_bucket(float e) {
    int b = (int)(e * HSCALE);
    return min(max(b, 0), HB - 1);
}
__device__ __forceinline__ unsigned tf32_rnd(float x) {
    unsigned r;
    asm("cvt.rna.tf32.f32 %0, %1;" : "=r"(r) : "f"(x));
    return r;
}
__device__ __forceinline__ void mma8(float* d, const unsigned* a,
                                     unsigned b0, unsigned b1) {
    asm volatile(
        "mma.sync.aligned.m16n8k8.row.col.f32.tf32.tf32.f32 "
        "{%0,%1,%2,%3},{%4,%5,%6,%7},{%8,%9},{%0,%1,%2,%3};"
        : "+f"(d[0]), "+f"(d[1]), "+f"(d[2]), "+f"(d[3])
        : "r"(a[0]), "r"(a[1]), "r"(a[2]), "r"(a[3]), "r"(b0), "r"(b1));
}
__device__ __forceinline__ void mma16(float* d, const unsigned* a,
                                      unsigned b0, unsigned b1) {
    asm volatile(
        "mma.sync.aligned.m16n8k16.row.col.f32.bf16.bf16.f32 "
        "{%0,%1,%2,%3},{%4,%5,%6,%7},{%8,%9},{%0,%1,%2,%3};"
        : "+f"(d[0]), "+f"(d[1]), "+f"(d[2]), "+f"(d[3])
        : "r"(a[0]), "r"(a[1]), "r"(a[2]), "r"(a[3]), "r"(b0), "r"(b1));
}
__device__ __forceinline__ unsigned packbf(float e, float o) {
    unsigned r;
    asm("cvt.rn.bf16x2.f32 %0, %1, %2;" : "=r"(r) : "f"(o), "f"(e));
    return r;
}
__device__ __forceinline__ void split2(float e, float o, unsigned &hi, unsigned &lo) {
    hi = packbf(e, o);
    float fe = __uint_as_float(hi << 16);
    float fo = __uint_as_float(hi & 0xffff0000u);
    lo = packbf(e - fe, o - fo);
}
__device__ __forceinline__ void cpa16(unsigned dst, const void* src) {
    asm volatile("cp.async.ca.shared.global [%0], [%1], 16;" :: "r"(dst), "l"(src));
}
#define CP_COMMIT() asm volatile("cp.async.commit_group;")
#define CP_WAIT1()  asm volatile("cp.async.wait_group 1;")
#define CP_WAIT0()  asm volatile("cp.async.wait_group 0;")

// ---------------- 1) warmup stats + W split + state reset ----------------
__global__ void k_warmup(const float* __restrict__ W, const float* __restrict__ b) {
    int c1 = blockIdx.x, tid = threadIdx.x;     // 50 blocks x 64
    __shared__ float sw[DD];
    __shared__ float sl[CC];
    for (int k = tid; k < DD; k += 64) sw[k] = W[(size_t)c1 * DD + k];
    __syncthreads();
    if (tid < CC) {
        const float* wj = W + (size_t)tid * DD;
        float acc = 0.f;
        for (int k = 0; k < DD; k++) acc += sw[k] * wj[k];
        sl[tid] = acc + b[tid];
    }
    __syncthreads();
    if (tid == 0) {
        float mx = sl[0]; int arg = 0;
        for (int c = 1; c < CC; c++) if (sl[c] > mx) { mx = sl[c]; arg = c; }
        float se = 0.f, sw2 = 0.f;
        for (int c = 0; c < CC; c++) {
            float e = __expf(sl[c] - mx);
            se += e; sw2 += e * sl[c];
        }
        float lse = mx + __logf(se);
        g_ent[c1]  = lse - sw2 / se;
        g_conf[c1] = 1.0f / se;
        g_lab[c1]  = arg;
    }
    int g = blockIdx.x * 64 + tid;
    for (int i = g; i < HB; i += CC * 64) g_hist16[i] = 0u;
    for (int idx = g; idx < DD * NPADB; idx += CC * 64) {   // W^T tf32-hi split
        int k = idx / NPADB, c = idx % NPADB;
        float x = (c < CC) ? W[(size_t)c * DD + k] : 0.f;
        g_WThi[idx] = __uint_as_float(tf32_rnd(x));
    }
    if (c1 == 0 && tid == 0) {
        g_sum_ent = 0.0;
        g_cand_n[0] = 0; g_cand_n[1] = 0;
        g_done = 0;
        g_thr_flag = 0;
        g_valid_n = 0;
    }
}

// ---------------- 2) main GEMM (1xTF32) + stats + superset compaction -----
__global__ __launch_bounds__(TPB, 4)
void k_main(const float* __restrict__ feat, const float* __restrict__ lraw,
            const float* __restrict__ laug, const float* __restrict__ b) {
    extern __shared__ float smem[];
    __shared__ double red[TPB];
    int tid = threadIdx.x;
    int lane = tid & 31, wb = (tid >> 5) * 16, r4 = lane >> 2, q4 = lane & 3;
    unsigned sb = (unsigned)__cvta_generic_to_shared(smem);
    const float* featBase = feat + (size_t)blockIdx.x * BROWS * DD;

    if (tid < NPADB) smem[MAIN_BIAS + tid] = (tid < CC) ? b[tid] : 0.f;

    float acc[28];
#pragma unroll
    for (int j = 0; j < 28; j++) acc[j] = 0.f;
    float norm0 = 0.f, norm1 = 0.f;

#define ISSUE_MAIN(kc, bf)                                                       \
    {                                                                            \
        int _kc = (kc), _bf = (bf);                                              \
        _Pragma("unroll")                                                        \
        for (int n = 0; n < 4; n++) {                                            \
            int i = tid + n * TPB;           /* 128 rows x 8 quads */            \
            int row = i >> 3, q = i & 7;                                         \
            cpa16(sb + (unsigned)(_bf * ASTAGE + row * A_STRIDE + q * 4) * 4u,   \
                  featBase + (size_t)row * DD + _kc * 32 + q * 4);               \
        }                                                                        \
        for (int i = tid; i < 448; i += TPB) {                                   \
            int row = i / 14, q = i % 14;                                        \
            cpa16(sb + (unsigned)(MAIN_BH + _bf * 1792 + row * NPADB + q * 4) * 4u,\
                  g_WThi + (size_t)(_kc * 32 + row) * NPADB + q * 4);            \
        }                                                                        \
    }

    ISSUE_MAIN(0, 0);
    CP_COMMIT();
#pragma unroll 1
    for (int c = 0; c < 16; ++c) {
        int bf = c & 1;
        if (c + 1 < 16) {
            ISSUE_MAIN(c + 1, (c + 1) & 1);
            CP_COMMIT();
            CP_WAIT1();
        } else {
            CP_WAIT0();
        }
        __syncthreads();
        const float* sA  = smem + bf * ASTAGE;
        const float* sBH = smem + MAIN_BH + bf * 1792;
#pragma unroll
        for (int kt = 0; kt < 4; kt++) {
            int k0 = kt * 8 + q4;
            float af[4];
            af[0] = sA[(wb + r4) * A_STRIDE + k0];
            af[1] = sA[(wb + r4 + 8) * A_STRIDE + k0];
            af[2] = sA[(wb + r4) * A_STRIDE + k0 + 4];
            af[3] = sA[(wb + r4 + 8) * A_STRIDE + k0 + 4];
            unsigned ahi[4];
#pragma unroll
            for (int j = 0; j < 4; j++) ahi[j] = tf32_rnd(af[j]);
            norm0 = fmaf(af[0], af[0], fmaf(af[2], af[2], norm0));
            norm1 = fmaf(af[1], af[1], fmaf(af[3], af[3], norm1));
#pragma unroll
            for (int nt = 0; nt < NT; nt++) {
                int bi = k0 * NPADB + nt * 8 + r4;
                unsigned bh0 = __float_as_uint(sBH[bi]);
                unsigned bh1 = __float_as_uint(sBH[bi + 4 * NPADB]);
                mma8(acc + nt * 4, ahi, bh0, bh1);
            }
        }
        __syncthreads();
    }
#undef ISSUE_MAIN

    // norms: reduce across quad, store per row
    norm0 += __shfl_xor_sync(0xffffffffu, norm0, 1);
    norm0 += __shfl_xor_sync(0xffffffffu, norm0, 2);
    norm1 += __shfl_xor_sync(0xffffffffu, norm1, 1);
    norm1 += __shfl_xor_sync(0xffffffffu, norm1, 2);
    if (q4 == 0) {
        smem[MAIN_NORM + wb + r4]     = norm0;
        smem[MAIN_NORM + wb + 8 + r4] = norm1;
    }

    // ---- dual-view argmax consistency (staged coalesced in A region) ----
    int i1 = 0, i2 = 0;
    {
        const float* srcR = lraw + (size_t)blockIdx.x * BROWS * CC;
        for (int i = tid; i < BROWS * CC; i += TPB) smem[i] = srcR[i];
        __syncthreads();
        if (tid < BROWS) {
            const float* rr = smem + tid * CC;
            float b1 = -3.4e38f;
#pragma unroll
            for (int c = 0; c < CC; c++)
                if (rr[c] > b1) { b1 = rr[c]; i1 = c; }
        }
        __syncthreads();
        const float* srcA = laug + (size_t)blockIdx.x * BROWS * CC;
        for (int i = tid; i < BROWS * CC; i += TPB) smem[i] = srcA[i];
        __syncthreads();
        if (tid < BROWS) {
            const float* rr = smem + tid * CC;
            float b2 = -3.4e38f;
#pragma unroll
            for (int c = 0; c < CC; c++)
                if (rr[c] > b2) { b2 = rr[c]; i2 = c; }
        }
        __syncthreads();
    }

    // scatter logit fragments to smem [row][58] (A region reused)
#pragma unroll
    for (int nt = 0; nt < NT; nt++) {
        int row = wb + r4;
        int col = nt * 8 + q4 * 2;
        const float* d = acc + nt * 4;
        *(float2*)(smem + row * SL_STRIDE + col) = make_float2(d[0], d[1]);
        *(float2*)(smem + (row + 8) * SL_STRIDE + col) = make_float2(d[2], d[3]);
    }
    __syncthreads();

    // ---- exact fp32 per-row epilogue (no arrays: two smem passes) ----
    float ent = 0.f;
    if (tid < BROWS) {
        int grow = blockIdx.x * BROWS + tid;
        const float* lrow = smem + tid * SL_STRIDE;
        const float* brow = smem + MAIN_BIAS;
        float mx = -3.4e38f; int arg = 0;
#pragma unroll
        for (int c = 0; c < CC; c++) {
            float v = lrow[c] + brow[c];
            if (v > mx) { mx = v; arg = c; }
        }
        float se = 0.f, sl = 0.f;
#pragma unroll
        for (int c = 0; c < CC; c++) {
            float v = lrow[c] + brow[c];
            float e = __expf(v - mx);
            se += e; sl += e * v;
        }
        float lse  = mx + __logf(se);
        ent        = lse - sl / se;
        float pmax = 1.0f / se;
        float inv  = 1.0f / fmaxf(sqrtf(smem[MAIN_NORM + tid]), 1e-12f);

        g_ent[CC + grow]  = ent;
        g_conf[CC + grow] = pmax;
        g_lab[CC + grow]  = arg;
        g_scale[grow]     = 20.0f * inv;
        atomicAdd(&g_hist16[ent_bucket(ent)], 1u);

        // superset compaction: consist && conf >= 0.62 (looser of both branches)
        if ((i1 == i2) && (pmax >= 0.62f)) {
            int p = atomicAdd(&g_valid_n, 1);
            g_valid_idx[p] = CC + grow;
        }
    }

    red[tid] = (tid < BROWS) ? (double)ent : 0.0;
    __syncthreads();
    for (int s = TPB / 2; s; s >>= 1) {
        if (tid < s) red[tid] += red[tid + s];
        __syncthreads();
    }
    if (tid == 0) atomicAdd(&g_sum_ent, red[0]);
}

// ---- 3) fused: scan+gather+pick (blocks 0-255) | topk+centroid (256-305) --
__global__ void k_spc(const float* __restrict__ feat, const float* __restrict__ W) {
    __shared__ unsigned sc[256];
    __shared__ int   s_bucket[2], s_rwith[2];
    __shared__ float qv[2];
    __shared__ int   s_last;
    __shared__ unsigned long long sh[256];
    __shared__ int   s_idx[FK];
    __shared__ float s_w[FK];
    __shared__ float scol[2 * 256];
    __shared__ float red[256];
    int tid = threadIdx.x;
    int bid = blockIdx.x;

    if (bid < 256) {
        // ---- branch params (deterministic, per block) ----
        float m = (float)(g_sum_ent / (double)BN);
        float q = (m >= 0.45f) ? 0.25f : ((m >= 0.38f) ? 0.3f : 0.4f);
        float pos = q * (float)(BN - 1);
        float lof = floorf(pos);
        float frac = pos - lof;
        int ranks[2];
        ranks[0] = (int)lof;
        ranks[1] = min((int)lof + 1, BN - 1);

        // ---- block-local scan: 256 threads x 32 bins ----
        int base = tid * 32;
        unsigned local = 0;
#pragma unroll
        for (int j = 0; j < 32; j += 4) {
            uint4 h = *(const uint4*)&g_hist16[base + j];
            local += h.x + h.y + h.z + h.w;
        }
        sc[tid] = local;
        __syncthreads();
        for (int off = 1; off < 256; off <<= 1) {
            unsigned v = 0;
            if (tid >= off) v = sc[tid - off];
            __syncthreads();
            if (tid >= off) sc[tid] += v;
            __syncthreads();
        }
        unsigned incl = sc[tid];
        unsigned before = incl - local;
#pragma unroll
        for (int s = 0; s < 2; s++) {
            unsigned r = (unsigned)ranks[s];
            if (before <= r && r < incl) {
                unsigned acc = before;
                for (int j = 0; j < 32; j++) {
                    unsigned c = g_hist16[base + j];
                    if (r < acc + c) {
                        s_bucket[s] = base + j;
                        s_rwith[s]  = (int)(r - acc);
                        break;
                    }
                    acc += c;
                }
            }
        }
        __syncthreads();

        // ---- gather (one element per thread) ----
        int i = bid * 256 + tid;
        int b0 = s_bucket[0], b1 = s_bucket[1];
        float e = g_ent[CC + i];
        int bb = ent_bucket(e);
        if (bb == b0) {
            int p = atomicAdd(&g_cand_n[0], 1);
            if (p < CAP) g_cand[0][p] = e;
        }
        if (bb == b1) {
            int p = atomicAdd(&g_cand_n[1], 1);
            if (p < CAP) g_cand[1][p] = e;
        }
        __threadfence();
        __syncthreads();
        if (tid == 0) s_last = (atomicAdd(&g_done, 1) == 255);
        __syncthreads();
        if (!s_last) return;
        __threadfence();

        // ---- tail block: exact rank pick ----
        for (int s = 0; s < 2; s++) {
            int n = min(atomicAdd(&g_cand_n[s], 0), CAP);
            int r = s_rwith[s];
            for (int k = tid; k < n; k += 256) {
                float v = g_cand[s][k];
                int rank = 0;
                for (int j = 0; j < n; j++) {
                    float u = g_cand[s][j];
                    rank += (u < v) || (u == v && j < k);
                }
                if (rank == r) qv[s] = v;
            }
            __syncthreads();
        }
        if (tid == 0) {
            g_conf_thr = (m >= 0.45f) ? 0.72f : 0.62f;
            g_thr = qv[0] * (1.0f - frac) + qv[1] * frac;
            __threadfence();
            atomicExch(&g_thr_flag, 1);
        }
        return;
    }

    // ---------------- centroid blocks: class c = bid - 256 ----------------
    int c = bid - 256;
    if (tid == 0) {
        volatile int* vf = &g_thr_flag;
        while (*vf == 0) __nanosleep(100);
    }
    __syncthreads();
    __threadfence();

    float thr = g_thr, cthr = g_conf_thr;
    int nv = g_valid_n;

    unsigned long long loc[FK];
#pragma unroll
    for (int j = 0; j < FK; j++) loc[j] = ~0ull;

    for (int t = tid; t < CC + nv; t += 256) {
        int e = (t < CC) ? t : g_valid_idx[t - CC];
        if (g_lab[e] != c) continue;
        if (e >= CC && ((g_ent[e] > thr) || (g_conf[e] < cthr))) continue;
        unsigned long long k =
            (((unsigned long long)fkey(g_ent[e])) << 32) | (unsigned)e;
        if (k < loc[FK - 1]) {
            loc[FK - 1] = k;
#pragma unroll
            for (int j = FK - 1; j > 0; j--) {
                if (loc[j] < loc[j - 1]) {
                    unsigned long long t2 = loc[j];
                    loc[j] = loc[j - 1];
                    loc[j - 1] = t2;
                }
            }
        }
    }

    int ptr = 0;
    for (int j = 0; j < FK; j++) {
        sh[tid] = (ptr < FK) ? loc[ptr] : ~0ull;
        __syncthreads();
        for (int s = 128; s; s >>= 1) {
            if (tid < s) {
                unsigned long long x = sh[tid], y = sh[tid + s];
                sh[tid] = (y < x) ? y : x;
            }
            __syncthreads();
        }
        unsigned long long win = sh[0];
        __syncthreads();
        if (ptr < FK && loc[ptr] == win && win != ~0ull) ptr++;
        if (tid == 0) {
            if (win != ~0ull) {
                int idx = (int)(win & 0xffffffffu);
                s_idx[j] = idx;
                s_w[j]   = fmaxf(g_conf[idx], 1e-6f);
            } else {
                s_idx[j] = -1;
            }
        }
        __syncthreads();
    }

    float a0 = 0.f, a1 = 0.f;
    for (int j = 0; j < FK; j++) {
        int idx = s_idx[j];
        if (idx >= 0) {
            const float* v = (idx < CC) ? (W + (size_t)idx * DD)
                                        : (feat + (size_t)(idx - CC) * DD);
            float x0 = v[tid], x1 = v[tid + 256];
            red[tid] = x0 * x0 + x1 * x1;
            __syncthreads();
            for (int s = 128; s; s >>= 1) {
                if (tid < s) red[tid] += red[tid + s];
                __syncthreads();
            }
            float w = s_w[j] / fmaxf(sqrtf(red[0]), 1e-12f);
            __syncthreads();
            a0 += w * x0;
            a1 += w * x1;
        }
    }
    red[tid] = a0 * a0 + a1 * a1;
    __syncthreads();
    for (int s = 128; s; s >>= 1) {
        if (tid < s) red[tid] += red[tid + s];
        __syncthreads();
    }
    float n = fmaxf(sqrtf(red[0]), 1e-12f);
    scol[tid]       = a0 / n;
    scol[tid + 256] = a1 / n;
    __syncthreads();
    {
        float e = scol[2 * tid], o = scol[2 * tid + 1];
        unsigned hi, lo;
        split2(e, o, hi, lo);
        g_CBhi[(size_t)tid * NPADB + c] = hi;
        g_CBlo[(size_t)tid * NPADB + c] = lo;
    }
    if (c == 0) {
#pragma unroll
        for (int p = CC; p < NPADB; p++) {
            g_CBhi[(size_t)tid * NPADB + p] = 0u;
            g_CBlo[(size_t)tid * NPADB + p] = 0u;
        }
    }
}

// ---------------- 4) output GEMM (pure, 3-term bf16-split) ----------------
__global__ __launch_bounds__(TPB, 4)
void k_out(const float* __restrict__ feat, float* __restrict__ out) {
    extern __shared__ float smem[];
    int tid = threadIdx.x;
    int lane = tid & 31, wb = (tid >> 5) * 16, r4 = lane >> 2, q4 = lane & 3;
    unsigned sb = (unsigned)__cvta_generic_to_shared(smem);
    const float* featBase = feat + (size_t)blockIdx.x * BROWS * DD;

#define ISSUE_A(kc, bf)                                                          \
    {                                                                            \
        int _kc = (kc), _bf = (bf);                                              \
        _Pragma("unroll")                                                        \
        for (int n = 0; n < 4; n++) {                                            \
            int i = tid + n * TPB;                                               \
            int row = i >> 3, q = i & 7;                                         \
            cpa16(sb + (unsigned)(_bf * ASTAGE + row * A_STRIDE + q * 4) * 4u,   \
                  featBase + (size_t)row * DD + _kc * 32 + q * 4);               \
        }                                                                        \
    }
#define ISSUE_B(kc, bf)                                                          \
    if (tid < 224) {                                                             \
        int _kc = (kc), _bf = (bf);                                              \
        int row = tid / 14, q = tid % 14;                                        \
        cpa16(sb + (unsigned)(OUT_BHI + _bf * 896 + row * NPADB + q * 4) * 4u,   \
              g_CBhi + (size_t)(_kc * 16 + row) * NPADB + q * 4);                \
        cpa16(sb + (unsigned)(OUT_BLO + _bf * 896 + row * NPADB + q * 4) * 4u,   \
              g_CBlo + (size_t)(_kc * 16 + row) * NPADB + q * 4);                \
    }

    ISSUE_A(0, 0); ISSUE_B(0, 0);
    CP_COMMIT();
    ISSUE_A(1, 1); ISSUE_B(1, 1);
    CP_COMMIT();

    float acc[28];
#pragma unroll
    for (int j = 0; j < 28; j++) acc[j] = 0.f;

#pragma unroll 1
    for (int c = 0; c < 16; ++c) {
        int bf = c & 1;
        if (c >= 14) { CP_WAIT0(); } else { CP_WAIT1(); }
        __syncthreads();
        const float* sA = smem + bf * ASTAGE;
        const unsigned* sBH = (const unsigned*)(smem + OUT_BHI + bf * 896);
        const unsigned* sBL = (const unsigned*)(smem + OUT_BLO + bf * 896);
#pragma unroll
        for (int kt = 0; kt < 2; kt++) {
            int k0 = kt * 16 + 2 * q4;
            unsigned ahi[4], alo[4];
            {
                int rb = wb + r4;
                float2 x0 = *(const float2*)&sA[rb * A_STRIDE + k0];
                float2 x1 = *(const float2*)&sA[(rb + 8) * A_STRIDE + k0];
                float2 x2 = *(const float2*)&sA[rb * A_STRIDE + k0 + 8];
                float2 x3 = *(const float2*)&sA[(rb + 8) * A_STRIDE + k0 + 8];
                split2(x0.x, x0.y, ahi[0], alo[0]);
                split2(x1.x, x1.y, ahi[1], alo[1]);
                split2(x2.x, x2.y, ahi[2], alo[2]);
                split2(x3.x, x3.y, ahi[3], alo[3]);
            }
#pragma unroll
            for (int nt = 0; nt < NT; nt++) {
                int n = nt * 8 + r4;
                int kp = kt * 8 + q4;
                unsigned bh0 = sBH[kp * NPADB + n];
                unsigned bh1 = sBH[(kp + 4) * NPADB + n];
                unsigned bl0 = sBL[kp * NPADB + n];
                unsigned bl1 = sBL[(kp + 4) * NPADB + n];
                float* d0 = acc + nt * 4;
                mma16(d0, ahi, bh0, bh1);
                mma16(d0, alo, bh0, bh1);
                mma16(d0, ahi, bl0, bl1);
            }
        }
        __syncthreads();
        if (c + 2 < 16) {                         // refill THIS buffer
            ISSUE_A(c + 2, bf); ISSUE_B(c + 2, bf);
            CP_COMMIT();
        }
    }
#undef ISSUE_A
#undef ISSUE_B

#pragma unroll
    for (int nt = 0; nt < NT; nt++) {
        int row = wb + r4;
        int col = nt * 8 + q4 * 2;
        const float* d = acc + nt * 4;
        *(float2*)(smem + row * SL_STRIDE + col) = make_float2(d[0], d[1]);
        *(float2*)(smem + (row + 8) * SL_STRIDE + col) = make_float2(d[2], d[3]);
    }
    __syncthreads();

    if (tid < BROWS) {
        int grow = blockIdx.x * BROWS + tid;
        float s = g_scale[grow];
        float2* o2 = (float2*)(out + (size_t)grow * CC);
#pragma unroll
        for (int j = 0; j < CC / 2; j++) {
            float2 v;
            v.x = s * smem[tid * SL_STRIDE + 2 * j];
            v.y = s * smem[tid * SL_STRIDE + 2 * j + 1];
            o2[j] = v;
        }
    }
}

// ---------------- host ----------------
extern "C" void kernel_launch(void* const* d_in, const int* in_sizes, int n_in,
                              void* d_out, int out_size) {
    const float* feat = (const float*)d_in[0];
    const float* lraw = (const float*)d_in[1];
    const float* laug = (const float*)d_in[2];
    const float* W    = (const float*)d_in[3];
    const float* b    = (const float*)d_in[4];
    float* out = (float*)d_out;

    size_t sh_main = (size_t)SMEM_MAIN * sizeof(float);  // 51,968 B
    size_t sh_out  = (size_t)SMEM_OUT  * sizeof(float);  // 51,200 B
    cudaFuncSetAttribute(k_main, cudaFuncAttributeMaxDynamicSharedMemorySize, (int)sh_main);
    cudaFuncSetAttribute(k_out,  cudaFuncAttributeMaxDynamicSharedMemorySize, (int)sh_out);

    k_warmup<<<CC, 64>>>(W, b);                                 // 1
    k_main<<<BN / BROWS, TPB, sh_main>>>(feat, lraw, laug, b);  // 2
    k_spc<<<256 + CC, 256>>>(feat, W);                          // 3
    k_out<<<BN / BROWS, TPB, sh_out>>>(feat, out);              // 4 <- ncu window
}

// round 17
// speedup vs baseline: 1.0375x; 1.0236x over previous
#include <cuda_runtime.h>

#define BN 65536
#define DD 512
#define CC 50
#define NE (BN + CC)
#define FK 10
#define NPADB 56             // class dim padded to 56 (7 n-tiles of 8)
#define NT 7
#define TPB 256              // 8 warps
#define BROWS 128            // rows per GEMM block (1 m-tile of 16 per warp)
#define HB 8192
#define HSCALE 2048.0f
#define CAP 8192
#define CHUNK_TX 23552u      // 16384 (A) + 7168 (B) bytes per chunk

// smem float-offsets (BROWS=128)
#define A_STRIDE 36
#define ASTAGE   4608         // 128*36 per stage
#define MAIN_BH  9216         // + bf*1792
#define MAIN_NORM 12800
#define MAIN_BIAS 12928
#define BAR_MAIN 12992        // 2 u64 mbarriers (4 floats)
#define SMEM_MAIN 12996       // floats (51,984 B)
#define OUT_BHI  9216         // + bf*896 (u32)
#define OUT_BLO  11008        // + bf*896 (u32)
#define BAR_OUT  12800        // 2 u64 mbarriers
#define SMEM_OUT 12804        // floats (51,216 B)
#define SL_STRIDE 58          // logits at offset 0 (A region)

// ---------------- device state ----------------
__device__ double g_sum_ent;
__device__ float  g_ent[NE];
__device__ float  g_conf[NE];
__device__ int    g_lab[NE];
__device__ float  g_scale[BN];
__device__ __align__(16) unsigned g_hist16[HB];
__device__ int    g_cand_n[2];
__device__ int    g_done;
__device__ int    g_thr_flag;
__device__ int    g_valid_n;
__device__ int    g_valid_idx[BN];
__device__ float  g_cand[2][CAP];
__device__ float  g_thr, g_conf_thr;
__device__ __align__(16) float    g_WThi[DD * NPADB];       // W^T tf32-hi
__device__ __align__(16) unsigned g_CBhi[(DD / 2) * NPADB]; // centroids^T bf16x2 hi
__device__ __align__(16) unsigned g_CBlo[(DD / 2) * NPADB]; // centroids^T bf16x2 lo

// ---------------- helpers ----------------
__device__ __forceinline__ unsigned fkey(float f) {
    unsigned u = __float_as_uint(f);
    return (u & 0x80000000u) ? ~u : (u | 0x80000000u);
}
__device__ __forceinline__ int ent_bucket(float e) {
    int b = (int)(e * HSCALE);
    return min(max(b, 0), HB - 1);
}
__device__ __forceinline__ unsigned tf32_rnd(float x) {
    unsigned r;
    asm("cvt.rna.tf32.f32 %0, %1;" : "=r"(r) : "f"(x));
    return r;
}
__device__ __forceinline__ void mma8(float* d, const unsigned* a,
                                     unsigned b0, unsigned b1) {
    asm volatile(
        "mma.sync.aligned.m16n8k8.row.col.f32.tf32.tf32.f32 "
        "{%0,%1,%2,%3},{%4,%5,%6,%7},{%8,%9},{%0,%1,%2,%3};"
        : "+f"(d[0]), "+f"(d[1]), "+f"(d[2]), "+f"(d[3])
        : "r"(a[0]), "r"(a[1]), "r"(a[2]), "r"(a[3]), "r"(b0), "r"(b1));
}
__device__ __forceinline__ void mma16(float* d, const unsigned* a,
                                      unsigned b0, unsigned b1) {
    asm volatile(
        "mma.sync.aligned.m16n8k16.row.col.f32.bf16.bf16.f32 "
        "{%0,%1,%2,%3},{%4,%5,%6,%7},{%8,%9},{%0,%1,%2,%3};"
        : "+f"(d[0]), "+f"(d[1]), "+f"(d[2]), "+f"(d[3])
        : "r"(a[0]), "r"(a[1]), "r"(a[2]), "r"(a[3]), "r"(b0), "r"(b1));
}
__device__ __forceinline__ unsigned packbf(float e, float o) {
    unsigned r;
    asm("cvt.rn.bf16x2.f32 %0, %1, %2;" : "=r"(r) : "f"(o), "f"(e));
    return r;
}
__device__ __forceinline__ void split2(float e, float o, unsigned &hi, unsigned &lo) {
    hi = packbf(e, o);
    float fe = __uint_as_float(hi << 16);
    float fo = __uint_as_float(hi & 0xffff0000u);
    lo = packbf(e - fe, o - fo);
}
// ---- bulk async copy + mbarrier ----
__device__ __forceinline__ void cpbulk(unsigned dst, const void* src,
                                       unsigned bytes, unsigned mbar) {
    asm volatile(
        "cp.async.bulk.shared::cta.global.mbarrier::complete_tx::bytes "
        "[%0], [%1], %2, [%3];"
        :: "r"(dst), "l"(src), "r"(bytes), "r"(mbar) : "memory");
}
__device__ __forceinline__ void mbar_init(unsigned mbar, unsigned cnt) {
    asm volatile("mbarrier.init.shared.b64 [%0], %1;" :: "r"(mbar), "r"(cnt)
                 : "memory");
}
__device__ __forceinline__ void mbar_expect(unsigned mbar, unsigned bytes) {
    asm volatile("mbarrier.arrive.expect_tx.shared.b64 _, [%0], %1;"
                 :: "r"(mbar), "r"(bytes) : "memory");
}
__device__ __forceinline__ void mbar_wait(unsigned mbar, unsigned parity) {
    asm volatile(
        "{\n\t.reg .pred P;\n"
        "W%=:\n\tmbarrier.try_wait.parity.acquire.cta.shared::cta.b64 P, [%0], %1, 0x989680;\n"
        "\t@P bra D%=;\n\tbra W%=;\nD%=:\n\t}"
        :: "r"(mbar), "r"(parity) : "memory");
}

// ---------------- 1) warmup stats + W split + state reset ----------------
__global__ void k_warmup(const float* __restrict__ W, const float* __restrict__ b) {
    int c1 = blockIdx.x, tid = threadIdx.x;     // 50 blocks x 64
    __shared__ float sw[DD];
    __shared__ float sl[CC];
    for (int k = tid; k < DD; k += 64) sw[k] = W[(size_t)c1 * DD + k];
    __syncthreads();
    if (tid < CC) {
        const float* wj = W + (size_t)tid * DD;
        float acc = 0.f;
        for (int k = 0; k < DD; k++) acc += sw[k] * wj[k];
        sl[tid] = acc + b[tid];
    }
    __syncthreads();
    if (tid == 0) {
        float mx = sl[0]; int arg = 0;
        for (int c = 1; c < CC; c++) if (sl[c] > mx) { mx = sl[c]; arg = c; }
        float se = 0.f, sw2 = 0.f;
        for (int c = 0; c < CC; c++) {
            float e = __expf(sl[c] - mx);
            se += e; sw2 += e * sl[c];
        }
        float lse = mx + __logf(se);
        g_ent[c1]  = lse - sw2 / se;
        g_conf[c1] = 1.0f / se;
        g_lab[c1]  = arg;
    }
    int g = blockIdx.x * 64 + tid;
    for (int i = g; i < HB; i += CC * 64) g_hist16[i] = 0u;
    for (int idx = g; idx < DD * NPADB; idx += CC * 64) {   // W^T tf32-hi split
        int k = idx / NPADB, c = idx % NPADB;
        float x = (c < CC) ? W[(size_t)c * DD + k] : 0.f;
        g_WThi[idx] = __uint_as_float(tf32_rnd(x));
    }
    if (c1 == 0 && tid == 0) {
        g_sum_ent = 0.0;
        g_cand_n[0] = 0; g_cand_n[1] = 0;
        g_done = 0;
        g_thr_flag = 0;
        g_valid_n = 0;
    }
}

// ---------------- 2) main GEMM (1xTF32, bulk-async) + stats ---------------
__global__ __launch_bounds__(TPB, 3)
void k_main(const float* __restrict__ feat, const float* __restrict__ lraw,
            const float* __restrict__ laug, const float* __restrict__ b) {
    extern __shared__ float smem[];
    __shared__ double red[TPB];
    int tid = threadIdx.x;
    int lane = tid & 31, wb = (tid >> 5) * 16, r4 = lane >> 2, q4 = lane & 3;
    unsigned sb = (unsigned)__cvta_generic_to_shared(smem);
    const float* featBase = feat + (size_t)blockIdx.x * BROWS * DD;

    if (tid < NPADB) smem[MAIN_BIAS + tid] = (tid < CC) ? b[tid] : 0.f;
    if (tid == 0) {
        mbar_init(sb + (BAR_MAIN + 0) * 4u, 1);
        mbar_init(sb + (BAR_MAIN + 2) * 4u, 1);
    }
    __syncthreads();

    float acc[28];
#pragma unroll
    for (int j = 0; j < 28; j++) acc[j] = 0.f;
    float norm0 = 0.f, norm1 = 0.f;

#define ISSUE_MAIN(kc, bf)                                                       \
    {                                                                            \
        int _kc = (kc), _bf = (bf);                                              \
        unsigned _bar = sb + (unsigned)(BAR_MAIN + _bf * 2) * 4u;                \
        if (tid == 0) mbar_expect(_bar, CHUNK_TX);                               \
        if (tid < BROWS)                                                         \
            cpbulk(sb + (unsigned)(_bf * ASTAGE + tid * A_STRIDE) * 4u,          \
                   featBase + (size_t)tid * DD + _kc * 32, 128u, _bar);          \
        else if (tid == BROWS)                                                   \
            cpbulk(sb + (unsigned)(MAIN_BH + _bf * 1792) * 4u,                   \
                   g_WThi + (size_t)_kc * 32 * NPADB, 7168u, _bar);              \
    }

    ISSUE_MAIN(0, 0);
    ISSUE_MAIN(1, 1);
    int ph0 = 0, ph1 = 0;
#pragma unroll 1
    for (int c = 0; c < 16; ++c) {
        int bf = c & 1;
        unsigned bar = sb + (unsigned)(BAR_MAIN + bf * 2) * 4u;
        mbar_wait(bar, bf ? ph1 : ph0);
        if (bf) ph1 ^= 1; else ph0 ^= 1;
        const float* sA  = smem + bf * ASTAGE;
        const float* sBH = smem + MAIN_BH + bf * 1792;
#pragma unroll
        for (int kt = 0; kt < 4; kt++) {
            int k0 = kt * 8 + q4;
            float af[4];
            af[0] = sA[(wb + r4) * A_STRIDE + k0];
            af[1] = sA[(wb + r4 + 8) * A_STRIDE + k0];
            af[2] = sA[(wb + r4) * A_STRIDE + k0 + 4];
            af[3] = sA[(wb + r4 + 8) * A_STRIDE + k0 + 4];
            unsigned ahi[4];
#pragma unroll
            for (int j = 0; j < 4; j++) ahi[j] = tf32_rnd(af[j]);
            norm0 = fmaf(af[0], af[0], fmaf(af[2], af[2], norm0));
            norm1 = fmaf(af[1], af[1], fmaf(af[3], af[3], norm1));
#pragma unroll
            for (int nt = 0; nt < NT; nt++) {
                int bi = k0 * NPADB + nt * 8 + r4;
                unsigned bh0 = __float_as_uint(sBH[bi]);
                unsigned bh1 = __float_as_uint(sBH[bi + 4 * NPADB]);
                mma8(acc + nt * 4, ahi, bh0, bh1);
            }
        }
        __syncthreads();
        if (c + 2 < 16) ISSUE_MAIN(c + 2, bf);
    }
#undef ISSUE_MAIN

    // norms: reduce across quad, store per row
    norm0 += __shfl_xor_sync(0xffffffffu, norm0, 1);
    norm0 += __shfl_xor_sync(0xffffffffu, norm0, 2);
    norm1 += __shfl_xor_sync(0xffffffffu, norm1, 1);
    norm1 += __shfl_xor_sync(0xffffffffu, norm1, 2);
    if (q4 == 0) {
        smem[MAIN_NORM + wb + r4]     = norm0;
        smem[MAIN_NORM + wb + 8 + r4] = norm1;
    }

    // ---- dual-view argmax consistency (staged coalesced in A region) ----
    int i1 = 0, i2 = 0;
    {
        const float* srcR = lraw + (size_t)blockIdx.x * BROWS * CC;
        for (int i = tid; i < BROWS * CC; i += TPB) smem[i] = srcR[i];
        __syncthreads();
        if (tid < BROWS) {
            const float* rr = smem + tid * CC;
            float b1 = -3.4e38f;
#pragma unroll
            for (int c = 0; c < CC; c++)
                if (rr[c] > b1) { b1 = rr[c]; i1 = c; }
        }
        __syncthreads();
        const float* srcA = laug + (size_t)blockIdx.x * BROWS * CC;
        for (int i = tid; i < BROWS * CC; i += TPB) smem[i] = srcA[i];
        __syncthreads();
        if (tid < BROWS) {
            const float* rr = smem + tid * CC;
            float b2 = -3.4e38f;
#pragma unroll
            for (int c = 0; c < CC; c++)
                if (rr[c] > b2) { b2 = rr[c]; i2 = c; }
        }
        __syncthreads();
    }

    // scatter logit fragments to smem [row][58] (A region reused)
#pragma unroll
    for (int nt = 0; nt < NT; nt++) {
        int row = wb + r4;
        int col = nt * 8 + q4 * 2;
        const float* d = acc + nt * 4;
        *(float2*)(smem + row * SL_STRIDE + col) = make_float2(d[0], d[1]);
        *(float2*)(smem + (row + 8) * SL_STRIDE + col) = make_float2(d[2], d[3]);
    }
    __syncthreads();

    // ---- exact fp32 per-row epilogue (no arrays: two smem passes) ----
    float ent = 0.f;
    if (tid < BROWS) {
        int grow = blockIdx.x * BROWS + tid;
        const float* lrow = smem + tid * SL_STRIDE;
        const float* brow = smem + MAIN_BIAS;
        float mx = -3.4e38f; int arg = 0;
#pragma unroll
        for (int c = 0; c < CC; c++) {
            float v = lrow[c] + brow[c];
            if (v > mx) { mx = v; arg = c; }
        }
        float se = 0.f, sl = 0.f;
#pragma unroll
        for (int c = 0; c < CC; c++) {
            float v = lrow[c] + brow[c];
            float e = __expf(v - mx);
            se += e; sl += e * v;
        }
        float lse  = mx + __logf(se);
        ent        = lse - sl / se;
        float pmax = 1.0f / se;
        float inv  = 1.0f / fmaxf(sqrtf(smem[MAIN_NORM + tid]), 1e-12f);

        g_ent[CC + grow]  = ent;
        g_conf[CC + grow] = pmax;
        g_lab[CC + grow]  = arg;
        g_scale[grow]     = 20.0f * inv;
        atomicAdd(&g_hist16[ent_bucket(ent)], 1u);

        // superset compaction: consist && conf >= 0.62 (looser of both branches)
        if ((i1 == i2) && (pmax >= 0.62f)) {
            int p = atomicAdd(&g_valid_n, 1);
            g_valid_idx[p] = CC + grow;
        }
    }

    red[tid] = (tid < BROWS) ? (double)ent : 0.0;
    __syncthreads();
    for (int s = TPB / 2; s; s >>= 1) {
        if (tid < s) red[tid] += red[tid + s];
        __syncthreads();
    }
    if (tid == 0) atomicAdd(&g_sum_ent, red[0]);
}

// ---- 3) fused: scan+gather+pick (blocks 0-255) | topk+centroid (256-305) --
__global__ void k_spc(const float* __restrict__ feat, const float* __restrict__ W) {
    __shared__ unsigned sc[256];
    __shared__ int   s_bucket[2], s_rwith[2];
    __shared__ float qv[2];
    __shared__ int   s_last;
    __shared__ unsigned long long sh[256];
    __shared__ int   s_idx[FK];
    __shared__ float s_w[FK];
    __shared__ float scol[2 * 256];
    __shared__ float red[256];
    int tid = threadIdx.x;
    int bid = blockIdx.x;

    if (bid < 256) {
        float m = (float)(g_sum_ent / (double)BN);
        float q = (m >= 0.45f) ? 0.25f : ((m >= 0.38f) ? 0.3f : 0.4f);
        float pos = q * (float)(BN - 1);
        float lof = floorf(pos);
        float frac = pos - lof;
        int ranks[2];
        ranks[0] = (int)lof;
        ranks[1] = min((int)lof + 1, BN - 1);

        int base = tid * 32;
        unsigned local = 0;
#pragma unroll
        for (int j = 0; j < 32; j += 4) {
            uint4 h = *(const uint4*)&g_hist16[base + j];
            local += h.x + h.y + h.z + h.w;
        }
        sc[tid] = local;
        __syncthreads();
        for (int off = 1; off < 256; off <<= 1) {
            unsigned v = 0;
            if (tid >= off) v = sc[tid - off];
            __syncthreads();
            if (tid >= off) sc[tid] += v;
            __syncthreads();
        }
        unsigned incl = sc[tid];
        unsigned before = incl - local;
#pragma unroll
        for (int s = 0; s < 2; s++) {
            unsigned r = (unsigned)ranks[s];
            if (before <= r && r < incl) {
                unsigned acc = before;
                for (int j = 0; j < 32; j++) {
                    unsigned c = g_hist16[base + j];
                    if (r < acc + c) {
                        s_bucket[s] = base + j;
                        s_rwith[s]  = (int)(r - acc);
                        break;
                    }
                    acc += c;
                }
            }
        }
        __syncthreads();

        int i = bid * 256 + tid;
        int b0 = s_bucket[0], b1 = s_bucket[1];
        float e = g_ent[CC + i];
        int bb = ent_bucket(e);
        if (bb == b0) {
            int p = atomicAdd(&g_cand_n[0], 1);
            if (p < CAP) g_cand[0][p] = e;
        }
        if (bb == b1) {
            int p = atomicAdd(&g_cand_n[1], 1);
            if (p < CAP) g_cand[1][p] = e;
        }
        __threadfence();
        __syncthreads();
        if (tid == 0) s_last = (atomicAdd(&g_done, 1) == 255);
        __syncthreads();
        if (!s_last) return;
        __threadfence();

        for (int s = 0; s < 2; s++) {
            int n = min(atomicAdd(&g_cand_n[s], 0), CAP);
            int r = s_rwith[s];
            for (int k = tid; k < n; k += 256) {
                float v = g_cand[s][k];
                int rank = 0;
                for (int j = 0; j < n; j++) {
                    float u = g_cand[s][j];
                    rank += (u < v) || (u == v && j < k);
                }
                if (rank == r) qv[s] = v;
            }
            __syncthreads();
        }
        if (tid == 0) {
            g_conf_thr = (m >= 0.45f) ? 0.72f : 0.62f;
            g_thr = qv[0] * (1.0f - frac) + qv[1] * frac;
            __threadfence();
            atomicExch(&g_thr_flag, 1);
        }
        return;
    }

    // ---------------- centroid blocks: class c = bid - 256 ----------------
    int c = bid - 256;
    if (tid == 0) {
        volatile int* vf = &g_thr_flag;
        while (*vf == 0) __nanosleep(100);
    }
    __syncthreads();
    __threadfence();

    float thr = g_thr, cthr = g_conf_thr;
    int nv = g_valid_n;

    unsigned long long loc[FK];
#pragma unroll
    for (int j = 0; j < FK; j++) loc[j] = ~0ull;

    for (int t = tid; t < CC + nv; t += 256) {
        int e = (t < CC) ? t : g_valid_idx[t - CC];
        if (g_lab[e] != c) continue;
        if (e >= CC && ((g_ent[e] > thr) || (g_conf[e] < cthr))) continue;
        unsigned long long k =
            (((unsigned long long)fkey(g_ent[e])) << 32) | (unsigned)e;
        if (k < loc[FK - 1]) {
            loc[FK - 1] = k;
#pragma unroll
            for (int j = FK - 1; j > 0; j--) {
                if (loc[j] < loc[j - 1]) {
                    unsigned long long t2 = loc[j];
                    loc[j] = loc[j - 1];
                    loc[j - 1] = t2;
                }
            }
        }
    }

    int ptr = 0;
    for (int j = 0; j < FK; j++) {
        sh[tid] = (ptr < FK) ? loc[ptr] : ~0ull;
        __syncthreads();
        for (int s = 128; s; s >>= 1) {
            if (tid < s) {
                unsigned long long x = sh[tid], y = sh[tid + s];
                sh[tid] = (y < x) ? y : x;
            }
            __syncthreads();
        }
        unsigned long long win = sh[0];
        __syncthreads();
        if (ptr < FK && loc[ptr] == win && win != ~0ull) ptr++;
        if (tid == 0) {
            if (win != ~0ull) {
                int idx = (int)(win & 0xffffffffu);
                s_idx[j] = idx;
                s_w[j]   = fmaxf(g_conf[idx], 1e-6f);
            } else {
                s_idx[j] = -1;
            }
        }
        __syncthreads();
    }

    float a0 = 0.f, a1 = 0.f;
    for (int j = 0; j < FK; j++) {
        int idx = s_idx[j];
        if (idx >= 0) {
            const float* v = (idx < CC) ? (W + (size_t)idx * DD)
                                        : (feat + (size_t)(idx - CC) * DD);
            float x0 = v[tid], x1 = v[tid + 256];
            red[tid] = x0 * x0 + x1 * x1;
            __syncthreads();
            for (int s = 128; s; s >>= 1) {
                if (tid < s) red[tid] += red[tid + s];
                __syncthreads();
            }
            float w = s_w[j] / fmaxf(sqrtf(red[0]), 1e-12f);
            __syncthreads();
            a0 += w * x0;
            a1 += w * x1;
        }
    }
    red[tid] = a0 * a0 + a1 * a1;
    __syncthreads();
    for (int s = 128; s; s >>= 1) {
        if (tid < s) red[tid] += red[tid + s];
        __syncthreads();
    }
    float n = fmaxf(sqrtf(red[0]), 1e-12f);
    scol[tid]       = a0 / n;
    scol[tid + 256] = a1 / n;
    __syncthreads();
    {
        float e = scol[2 * tid], o = scol[2 * tid + 1];
        unsigned hi, lo;
        split2(e, o, hi, lo);
        g_CBhi[(size_t)tid * NPADB + c] = hi;
        g_CBlo[(size_t)tid * NPADB + c] = lo;
    }
    if (c == 0) {
#pragma unroll
        for (int p = CC; p < NPADB; p++) {
            g_CBhi[(size_t)tid * NPADB + p] = 0u;
            g_CBlo[(size_t)tid * NPADB + p] = 0u;
        }
    }
}

// ------- 4) output GEMM (pure, 3-term bf16-split, bulk-async) -------------
__global__ __launch_bounds__(TPB, 4)
void k_out(const float* __restrict__ feat, float* __restrict__ out) {
    extern __shared__ float smem[];
    int tid = threadIdx.x;
    int lane = tid & 31, wb = (tid >> 5) * 16, r4 = lane >> 2, q4 = lane & 3;
    unsigned sb = (unsigned)__cvta_generic_to_shared(smem);
    const float* featBase = feat + (size_t)blockIdx.x * BROWS * DD;

    if (tid == 0) {
        mbar_init(sb + (BAR_OUT + 0) * 4u, 1);
        mbar_init(sb + (BAR_OUT + 2) * 4u, 1);
    }
    __syncthreads();

#define ISSUE_OUT(kc, bf)                                                        \
    {                                                                            \
        int _kc = (kc), _bf = (bf);                                              \
        unsigned _bar = sb + (unsigned)(BAR_OUT + _bf * 2) * 4u;                 \
        if (tid == 0) mbar_expect(_bar, CHUNK_TX);                               \
        if (tid < BROWS)                                                         \
            cpbulk(sb + (unsigned)(_bf * ASTAGE + tid * A_STRIDE) * 4u,          \
                   featBase + (size_t)tid * DD + _kc * 32, 128u, _bar);          \
        else if (tid == BROWS)                                                   \
            cpbulk(sb + (unsigned)(OUT_BHI + _bf * 896) * 4u,                    \
                   g_CBhi + (size_t)_kc * 16 * NPADB, 3584u, _bar);              \
        else if (tid == BROWS + 1)                                               \
            cpbulk(sb + (unsigned)(OUT_BLO + _bf * 896) * 4u,                    \
                   g_CBlo + (size_t)_kc * 16 * NPADB, 3584u, _bar);              \
    }

    ISSUE_OUT(0, 0);
    ISSUE_OUT(1, 1);

    float acc[28];
#pragma unroll
    for (int j = 0; j < 28; j++) acc[j] = 0.f;

    int ph0 = 0, ph1 = 0;
#pragma unroll 1
    for (int c = 0; c < 16; ++c) {
        int bf = c & 1;
        unsigned bar = sb + (unsigned)(BAR_OUT + bf * 2) * 4u;
        mbar_wait(bar, bf ? ph1 : ph0);
        if (bf) ph1 ^= 1; else ph0 ^= 1;
        const float* sA = smem + bf * ASTAGE;
        const unsigned* sBH = (const unsigned*)(smem + OUT_BHI + bf * 896);
        const unsigned* sBL = (const unsigned*)(smem + OUT_BLO + bf * 896);
#pragma unroll
        for (int kt = 0; kt < 2; kt++) {
            int k0 = kt * 16 + 2 * q4;
            unsigned ahi[4], alo[4];
            {
                int rb = wb + r4;
                float2 x0 = *(const float2*)&sA[rb * A_STRIDE + k0];
                float2 x1 = *(const float2*)&sA[(rb + 8) * A_STRIDE + k0];
                float2 x2 = *(const float2*)&sA[rb * A_STRIDE + k0 + 8];
                float2 x3 = *(const float2*)&sA[(rb + 8) * A_STRIDE + k0 + 8];
                split2(x0.x, x0.y, ahi[0], alo[0]);
                split2(x1.x, x1.y, ahi[1], alo[1]);
                split2(x2.x, x2.y, ahi[2], alo[2]);
                split2(x3.x, x3.y, ahi[3], alo[3]);
            }
#pragma unroll
            for (int nt = 0; nt < NT; nt++) {
                int n = nt * 8 + r4;
                int kp = kt * 8 + q4;
                unsigned bh0 = sBH[kp * NPADB + n];
                unsigned bh1 = sBH[(kp + 4) * NPADB + n];
                unsigned bl0 = sBL[kp * NPADB + n];
                unsigned bl1 = sBL[(kp + 4) * NPADB + n];
                float* d0 = acc + nt * 4;
                mma16(d0, ahi, bh0, bh1);
                mma16(d0, alo, bh0, bh1);
                mma16(d0, ahi, bl0, bl1);
            }
        }
        __syncthreads();
        if (c + 2 < 16) ISSUE_OUT(c + 2, bf);
    }
#undef ISSUE_OUT

#pragma unroll
    for (int nt = 0; nt < NT; nt++) {
        int row = wb + r4;
        int col = nt * 8 + q4 * 2;
        const float* d = acc + nt * 4;
        *(float2*)(smem + row * SL_STRIDE + col) = make_float2(d[0], d[1]);
        *(float2*)(smem + (row + 8) * SL_STRIDE + col) = make_float2(d[2], d[3]);
    }
    __syncthreads();

    if (tid < BROWS) {
        int grow = blockIdx.x * BROWS + tid;
        float s = g_scale[grow];
        float2* o2 = (float2*)(out + (size_t)grow * CC);
#pragma unroll
        for (int j = 0; j < CC / 2; j++) {
            float2 v;
            v.x = s * smem[tid * SL_STRIDE + 2 * j];
            v.y = s * smem[tid * SL_STRIDE + 2 * j + 1];
            o2[j] = v;
        }
    }
}

// ---------------- host ----------------
extern "C" void kernel_launch(void* const* d_in, const int* in_sizes, int n_in,
                              void* d_out, int out_size) {
    const float* feat = (const float*)d_in[0];
    const float* lraw = (const float*)d_in[1];
    const float* laug = (const float*)d_in[2];
    const float* W    = (const float*)d_in[3];
    const float* b    = (const float*)d_in[4];
    float* out = (float*)d_out;

    size_t sh_main = (size_t)SMEM_MAIN * sizeof(float);  // 51,984 B
    size_t sh_out  = (size_t)SMEM_OUT  * sizeof(float);  // 51,216 B
    cudaFuncSetAttribute(k_main, cudaFuncAttributeMaxDynamicSharedMemorySize, (int)sh_main);
    cudaFuncSetAttribute(k_out,  cudaFuncAttributeMaxDynamicSharedMemorySize, (int)sh_out);

    k_warmup<<<CC, 64>>>(W, b);                                 // 1
    k_main<<<BN / BROWS, TPB, sh_main>>>(feat, lraw, laug, b);  // 2
    k_spc<<<256 + CC, 256>>>(feat, W);                          // 3
    k_out<<<BN / BROWS, TPB, sh_out>>>(feat, out);              // 4 <- ncu window
}